// round 11
// baseline (speedup 1.0000x reference)
#include <cuda_runtime.h>
#include <math.h>
#include <stdint.h>

#define BATCH 2
#define CH 256
#define HH 56
#define WW 56
#define NP (HH*WW)        /* 3136 */
#define NPP 3200          /* padded token dim (25 * 128) */
#define NH 8
#define DH 32
#define KCNT1 1568        /* N1 // 2 */
#define KCNT2 1045        /* N1 // 3 */
#define LN_EPS 1e-5f
#define SCALE 0.17677669529663687f  /* 1/sqrt(32) */

typedef unsigned long long ull;

// packed f32x2 FMA: d = a*b + d (elementwise on 2 packed floats)
__device__ __forceinline__ void fma2(ull &d, ull a, ull b) {
    asm("fma.rn.f32x2 %0, %1, %2, %3;" : "=l"(d) : "l"(a), "l"(b), "l"(d));
}
__device__ __forceinline__ float2 up2(ull v) {
    float2 r; asm("mov.b64 {%0,%1}, %2;" : "=f"(r.x), "=f"(r.y) : "l"(v)); return r;
}

// ---------------- scratch (static device globals; no allocation) ------------
// Pad rows [NP, NPP) are NEVER written -> remain zero from static init.
__device__ __align__(16) float g_pool[BATCH*CH*NP];
__device__ __align__(16) float g_yln [BATCH*NP*CH];
__device__ __align__(16) float g_q   [BATCH*NH*NPP*DH];
__device__ __align__(16) float g_k   [BATCH*NH*NPP*DH];
__device__ __align__(16) float g_v   [BATCH*NH*NPP*DH];
__device__ __align__(16) float g_ao  [BATCH*NPP*CH];
__device__ __align__(16) float g_S   [(size_t)BATCH*NH*NPP*NPP];   // ~655 MB

// ---------------- 1) multiscale avg pool (3+5+7, zero-pad, divisor k^2) -----
__global__ __launch_bounds__(256) void pool_kernel(const float* __restrict__ y) {
    __shared__ float plane[NP];
    int bc = blockIdx.x;
    const float* src = y + (size_t)bc * NP;
    for (int i = threadIdx.x; i < NP; i += 256) plane[i] = src[i];
    __syncthreads();
    for (int i = threadIdx.x; i < NP; i += 256) {
        int r = i / WW, c = i % WW;
        float s3 = 0.f, s5 = 0.f, s7 = 0.f;
        #pragma unroll
        for (int dr = -3; dr <= 3; dr++) {
            int rr = r + dr; if (rr < 0 || rr >= HH) continue;
            #pragma unroll
            for (int dc = -3; dc <= 3; dc++) {
                int cc = c + dc; if (cc < 0 || cc >= WW) continue;
                float v = plane[rr*WW + cc];
                s7 += v;
                if (dr >= -2 && dr <= 2 && dc >= -2 && dc <= 2) s5 += v;
                if (dr >= -1 && dr <= 1 && dc >= -1 && dc <= 1) s3 += v;
            }
        }
        g_pool[(size_t)bc*NP + i] = s3*(1.f/9.f) + s5*(1.f/25.f) + s7*(1.f/49.f);
    }
}

// ---------------- 2) LayerNorm over channels -> yln [B,N,C] -----------------
__global__ __launch_bounds__(256) void ln_kernel(const float* __restrict__ ln_w,
                                                 const float* __restrict__ ln_b) {
    __shared__ float red[256];
    int bn = blockIdx.x;
    int b = bn / NP, n = bn % NP;
    int c = threadIdx.x;
    float v = g_pool[((size_t)b*CH + c)*NP + n];
    red[c] = v; __syncthreads();
    for (int off = 128; off > 0; off >>= 1) {
        if (c < off) red[c] += red[c + off];
        __syncthreads();
    }
    float mean = red[0] * (1.f/CH);
    __syncthreads();
    float dv = v - mean;
    red[c] = dv * dv; __syncthreads();
    for (int off = 128; off > 0; off >>= 1) {
        if (c < off) red[c] += red[c + off];
        __syncthreads();
    }
    float var = red[0] * (1.f/CH);
    g_yln[(size_t)bn*CH + c] = dv * rsqrtf(var + LN_EPS) * ln_w[c] + ln_b[c];
}

// ---------------- 3) KV GEMM: yln[B,N,C] x kv_w[512,C]^T -> k,v -------------
__global__ __launch_bounds__(256) void kv_gemm(const float* __restrict__ kv_w,
                                               const float* __restrict__ kv_b) {
    __shared__ float As[16][65];
    __shared__ float Bs[16][65];
    int b  = blockIdx.z;
    int m0 = blockIdx.x * 64;
    int o0 = blockIdx.y * 64;
    int tid = threadIdx.x, tx = tid & 15, ty = tid >> 4;
    float acc[4][4] = {};
    for (int k0 = 0; k0 < CH; k0 += 16) {
        #pragma unroll
        for (int l = 0; l < 4; l++) {
            int idx = tid + l*256; int k = idx & 15, m = idx >> 4;
            As[k][m] = g_yln[((size_t)b*NP + m0 + m)*CH + k0 + k];
        }
        #pragma unroll
        for (int l = 0; l < 4; l++) {
            int idx = tid + l*256; int k = idx & 15, o = idx >> 4;
            Bs[k][o] = kv_w[(size_t)(o0 + o)*CH + k0 + k];
        }
        __syncthreads();
        #pragma unroll
        for (int kk = 0; kk < 16; kk++) {
            float a[4], bb[4];
            #pragma unroll
            for (int i = 0; i < 4; i++) a[i]  = As[kk][ty*4 + i];
            #pragma unroll
            for (int j = 0; j < 4; j++) bb[j] = Bs[kk][tx*4 + j];
            #pragma unroll
            for (int i = 0; i < 4; i++)
                #pragma unroll
                for (int j = 0; j < 4; j++) acc[i][j] += a[i]*bb[j];
        }
        __syncthreads();
    }
    #pragma unroll
    for (int i = 0; i < 4; i++) {
        int n = m0 + ty*4 + i;
        #pragma unroll
        for (int j = 0; j < 4; j++) {
            int o = o0 + tx*4 + j;
            float r = acc[i][j] + kv_b[o];
            if (o < 256) {
                int hh = o >> 5, dd = o & 31;
                g_k[(((size_t)b*NH + hh)*NPP + n)*DH + dd] = r;
            } else {
                int oo = o - 256; int hh = oo >> 5, dd = oo & 31;
                g_v[(((size_t)b*NH + hh)*NPP + n)*DH + dd] = r;
            }
        }
    }
}

// ---------------- 4) Q GEMM: x[B,C,N] x q_w^T -------------------------------
__global__ __launch_bounds__(256) void q_gemm(const float* __restrict__ x,
                                              const float* __restrict__ q_w,
                                              const float* __restrict__ q_b) {
    __shared__ float As[16][65];
    __shared__ float Bs[16][65];
    int b  = blockIdx.z;
    int m0 = blockIdx.x * 64;
    int o0 = blockIdx.y * 64;
    const float* xb = x + (size_t)b*CH*NP;
    int tid = threadIdx.x, tx = tid & 15, ty = tid >> 4;
    float acc[4][4] = {};
    for (int k0 = 0; k0 < CH; k0 += 16) {
        #pragma unroll
        for (int l = 0; l < 4; l++) {
            int idx = tid + l*256; int m = idx & 63, k = idx >> 6;
            As[k][m] = xb[(size_t)(k0 + k)*NP + m0 + m];
        }
        #pragma unroll
        for (int l = 0; l < 4; l++) {
            int idx = tid + l*256; int k = idx & 15, o = idx >> 4;
            Bs[k][o] = q_w[(size_t)(o0 + o)*CH + k0 + k];
        }
        __syncthreads();
        #pragma unroll
        for (int kk = 0; kk < 16; kk++) {
            float a[4], bb[4];
            #pragma unroll
            for (int i = 0; i < 4; i++) a[i]  = As[kk][ty*4 + i];
            #pragma unroll
            for (int j = 0; j < 4; j++) bb[j] = Bs[kk][tx*4 + j];
            #pragma unroll
            for (int i = 0; i < 4; i++)
                #pragma unroll
                for (int j = 0; j < 4; j++) acc[i][j] += a[i]*bb[j];
        }
        __syncthreads();
    }
    #pragma unroll
    for (int i = 0; i < 4; i++) {
        int n = m0 + ty*4 + i;
        #pragma unroll
        for (int j = 0; j < 4; j++) {
            int o = o0 + tx*4 + j;
            int hh = o >> 5, dd = o & 31;
            g_q[(((size_t)b*NH + hh)*NPP + n)*DH + dd] = acc[i][j] + q_b[o];
        }
    }
}

// ====== shared helpers: bf16 split + mma.sync =================================
__device__ __forceinline__ void sc_bfsplit(float v, unsigned &hi16, unsigned &lo16) {
    unsigned u = __float_as_uint(v);
    unsigned t = u + 0x7FFFu + ((u >> 16) & 1u);
    hi16 = t >> 16;
    float r = v - __uint_as_float(hi16 << 16);
    unsigned ur = __float_as_uint(r);
    unsigned tr = ur + 0x7FFFu + ((ur >> 16) & 1u);
    lo16 = tr >> 16;
}

__device__ __forceinline__ void mma_bf16(float* d, const unsigned* a, const unsigned* b) {
    asm volatile(
        "mma.sync.aligned.m16n8k16.row.col.f32.bf16.bf16.f32 "
        "{%0,%1,%2,%3}, {%4,%5,%6,%7}, {%8,%9}, {%0,%1,%2,%3};"
        : "+f"(d[0]), "+f"(d[1]), "+f"(d[2]), "+f"(d[3])
        : "r"(a[0]), "r"(a[1]), "r"(a[2]), "r"(a[3]), "r"(b[0]), "r"(b[1]));
}

// ====== 5) scores via mma.sync bf16-split (128x128 tile, 8 warps) ===========
// A' = [q_hi | q_hi | q_lo] (K=96), B' = [k_hi | k_lo | k_hi] (K=96)
// D = q_hi*k_hi + q_hi*k_lo + q_lo*k_hi  (fp32 accumulate)

#define SC_STRIDE 52   /* 32-bit words per row: 48 data + 4 pad (conflict-free) */
#define SC_SMEM_BYTES (2 * 128 * SC_STRIDE * 4)

__global__ __launch_bounds__(256) void score_mma() {
    extern __shared__ unsigned sm32[];
    unsigned (*As)[SC_STRIDE] = (unsigned(*)[SC_STRIDE])sm32;              // q' [row][kw]
    unsigned (*Bs)[SC_STRIDE] = (unsigned(*)[SC_STRIDE])(sm32 + 128*SC_STRIDE); // k'

    int tid = threadIdx.x;
    int bh = blockIdx.z;
    int n0 = blockIdx.x * 128;
    int m0 = blockIdx.y * 128;

    // -------- load + split phase: 2048 chunks of 2 floats each --------------
    {
        const float* qb = g_q + ((size_t)bh*NPP + n0)*DH;
        const float* kb = g_k + ((size_t)bh*NPP + m0)*DH;
        #pragma unroll
        for (int l = 0; l < 8; l++) {
            int ch = tid + l*256;
            int row = ch >> 4, c2 = ch & 15;
            float2 qv = *(const float2*)(qb + (size_t)row*DH + 2*c2);
            float2 kv = *(const float2*)(kb + (size_t)row*DH + 2*c2);
            unsigned qh0, ql0, qh1, ql1, kh0, kl0, kh1, kl1;
            sc_bfsplit(qv.x, qh0, ql0); sc_bfsplit(qv.y, qh1, ql1);
            sc_bfsplit(kv.x, kh0, kl0); sc_bfsplit(kv.y, kh1, kl1);
            unsigned qh = qh0 | (qh1 << 16), ql = ql0 | (ql1 << 16);
            unsigned kh = kh0 | (kh1 << 16), kl = kl0 | (kl1 << 16);
            As[row][c2]      = qh;   // K 0..31 : q_hi
            As[row][16 + c2] = qh;   // K 32..63: q_hi
            As[row][32 + c2] = ql;   // K 64..95: q_lo
            Bs[row][c2]      = kh;   // K 0..31 : k_hi
            Bs[row][16 + c2] = kl;   // K 32..63: k_lo
            Bs[row][32 + c2] = kh;   // K 64..95: k_hi
        }
    }
    __syncthreads();

    // -------- compute phase: warp = 32 rows x 64 cols ----------------------
    int wid = tid >> 5, lane = tid & 31;
    int g = lane >> 2, tig = lane & 3;
    int warpM = wid & 3, warpN = wid >> 2;
    int mrow = warpM * 32;
    int ncol = warpN * 64;

    float acc[2][8][4];
    #pragma unroll
    for (int i = 0; i < 2; i++)
        #pragma unroll
        for (int j = 0; j < 8; j++)
            #pragma unroll
            for (int q = 0; q < 4; q++) acc[i][j][q] = 0.f;

    #pragma unroll
    for (int ks = 0; ks < 6; ks++) {
        int w0 = ks * 8;
        unsigned af[2][4];
        #pragma unroll
        for (int mt = 0; mt < 2; mt++) {
            int r = mrow + mt*16 + g;
            af[mt][0] = As[r][w0 + tig];
            af[mt][1] = As[r + 8][w0 + tig];
            af[mt][2] = As[r][w0 + tig + 4];
            af[mt][3] = As[r + 8][w0 + tig + 4];
        }
        #pragma unroll
        for (int nt = 0; nt < 8; nt++) {
            unsigned bf[2];
            int n = ncol + nt*8 + g;
            bf[0] = Bs[n][w0 + tig];
            bf[1] = Bs[n][w0 + tig + 4];
            mma_bf16(acc[0][nt], af[0], bf);
            mma_bf16(acc[1][nt], af[1], bf);
        }
    }

    // -------- epilogue -----------------------------------------------------
    float* outb = g_S + ((size_t)bh*NPP + n0)*NPP + m0;
    #pragma unroll
    for (int mt = 0; mt < 2; mt++) {
        int r0 = mrow + mt*16 + g;
        #pragma unroll
        for (int nt = 0; nt < 8; nt++) {
            int c = ncol + nt*8 + tig*2;
            float2 lo = make_float2(acc[mt][nt][0]*SCALE, acc[mt][nt][1]*SCALE);
            float2 hi = make_float2(acc[mt][nt][2]*SCALE, acc[mt][nt][3]*SCALE);
            *(float2*)(outb + (size_t)r0*NPP + c)       = lo;
            *(float2*)(outb + (size_t)(r0 + 8)*NPP + c) = hi;
        }
    }
}

// ---------------- 6) per-row exact top-k (fused hist0 + compaction) ---------
__device__ __forceinline__ unsigned block_suffix(unsigned h, int tid,
                                                 unsigned* wsum, unsigned* whigh) {
    unsigned v = h;
    int lane = tid & 31, w = tid >> 5;
    #pragma unroll
    for (int off = 1; off < 32; off <<= 1) {
        unsigned u = __shfl_down_sync(0xFFFFFFFFu, v, off);
        if (lane + off < 32) v += u;
    }
    if (lane == 0) wsum[w] = v;
    __syncthreads();
    if (tid == 0) {
        unsigned run = 0;
        for (int j = 7; j >= 0; j--) { whigh[j] = run; run += wsum[j]; }
    }
    __syncthreads();
    return v + whigh[w];
}

__global__ __launch_bounds__(256) void topk_kernel(const float* __restrict__ p1p,
                                                   const float* __restrict__ p2p) {
    __shared__ unsigned su[NP];        // transformed keys
    __shared__ unsigned comp[NP];      // candidates, later exp() cache
    __shared__ unsigned hist[256];
    __shared__ unsigned wsum[8], whigh[8];
    __shared__ float f8a[8], f8b[8];
    __shared__ unsigned selB_sh; __shared__ int selR_sh;
    __shared__ unsigned l0B[2];  __shared__ int l0R[2];
    __shared__ unsigned umax_sh;
    __shared__ unsigned cnt_sh;

    int bid = blockIdx.x;
    int head = bid / NP, n = bid % NP;
    float* base = g_S + ((size_t)head*NPP + n)*NPP;
    int tid = threadIdx.x;
    int lane = tid & 31, w = tid >> 5;

    hist[tid] = 0u;
    __syncthreads();

    // ---- load + transform + level-0 histogram (fused) + max ---------------
    unsigned lmax = 0u;
    const float4* b4 = (const float4*)base;
    for (int i = tid; i < NP/4; i += 256) {
        float4 v4 = b4[i];
        float vv[4] = {v4.x, v4.y, v4.z, v4.w};
        #pragma unroll
        for (int j = 0; j < 4; j++) {
            unsigned u = __float_as_uint(vv[j]);
            u ^= (u & 0x80000000u) ? 0xFFFFFFFFu : 0x80000000u;
            su[4*i + j] = u;
            atomicAdd(&hist[u >> 24], 1u);
            lmax = max(lmax, u);
        }
    }
    #pragma unroll
    for (int off = 16; off > 0; off >>= 1)
        lmax = max(lmax, __shfl_xor_sync(0xFFFFFFFFu, lmax, off));
    if (lane == 0) wsum[w] = lmax;
    __syncthreads();
    if (tid == 0) {
        unsigned m = 0u;
        for (int j = 0; j < 8; j++) m = max(m, wsum[j]);
        umax_sh = m;
    }
    __syncthreads();
    unsigned umax = umax_sh;
    float rowmax = __uint_as_float(umax ^ ((umax & 0x80000000u) ? 0x80000000u : 0xFFFFFFFFu));
    __syncthreads();   // umax latched before block_suffix reuses wsum

    // ---- level 0 (bits 31..24), shared by both selections -----------------
    {
        unsigned h = hist[tid];
        unsigned v = block_suffix(h, tid, wsum, whigh);
        if (v >= (unsigned)KCNT1 && v - h < (unsigned)KCNT1) {
            l0B[0] = (unsigned)tid; l0R[0] = KCNT1 - (int)(v - h);
        }
        if (v >= (unsigned)KCNT2 && v - h < (unsigned)KCNT2) {
            l0B[1] = (unsigned)tid; l0R[1] = KCNT2 - (int)(v - h);
        }
    }
    __syncthreads();

    // ---- levels 1..3 over compacted candidates ----------------------------
    unsigned thr_u[2];
    for (int s = 0; s < 2; s++) {
        unsigned myB = l0B[s];
        bool reuse = (s == 1) && (l0B[1] == l0B[0]);
        if (!reuse) {
            if (tid == 0) cnt_sh = 0u;
            __syncthreads();
            for (int i = tid; i < NP; i += 256) {
                unsigned u = su[i];
                if ((u >> 24) == myB) comp[atomicAdd(&cnt_sh, 1u)] = u;
            }
            __syncthreads();
        }
        int ncand = (int)cnt_sh;
        unsigned prefix = myB << 24;
        unsigned mask   = 0xFF000000u;
        int r = l0R[s];
        for (int shift = 16; shift >= 0; shift -= 8) {
            hist[tid] = 0u; __syncthreads();
            for (int i = tid; i < ncand; i += 256) {
                unsigned u = comp[i];
                if ((u & mask) == prefix)
                    atomicAdd(&hist[(u >> shift) & 255u], 1u);
            }
            __syncthreads();
            unsigned h = hist[tid];
            unsigned v = block_suffix(h, tid, wsum, whigh);
            if (v >= (unsigned)r && v - h < (unsigned)r) {
                selB_sh = (unsigned)tid;
                selR_sh = r - (int)(v - h);
            }
            __syncthreads();
            prefix |= selB_sh << shift;
            mask   |= 0xFFu << shift;
            r = selR_sh;
        }
        thr_u[s] = prefix;
    }

    // ---- Z1, Z2 (cache exp in comp) ---------------------------------------
    float z1 = 0.f, z2 = 0.f;
    for (int i = tid; i < NP; i += 256) {
        unsigned u = su[i];
        float v = __uint_as_float(u ^ ((u & 0x80000000u) ? 0x80000000u : 0xFFFFFFFFu));
        float e = __expf(v - rowmax);
        comp[i] = __float_as_uint(e);
        if (u >= thr_u[0]) z1 += e;
        if (u >= thr_u[1]) z2 += e;
    }
    #pragma unroll
    for (int off = 16; off > 0; off >>= 1) {
        z1 += __shfl_xor_sync(0xFFFFFFFFu, z1, off);
        z2 += __shfl_xor_sync(0xFFFFFFFFu, z2, off);
    }
    if (lane == 0) { f8a[w] = z1; f8b[w] = z2; }
    __syncthreads();
    float Z1 = 0.f, Z2 = 0.f;
    #pragma unroll
    for (int j = 0; j < 8; j++) { Z1 += f8a[j]; Z2 += f8b[j]; }

    // ---- write combined weights (vectorized, exp cached) ------------------
    float c1 = p1p[0] / Z1;
    float c2 = p2p[0] / Z2;
    for (int i = tid; i < NP/4; i += 256) {
        float o[4];
        #pragma unroll
        for (int j = 0; j < 4; j++) {
            unsigned u = su[4*i + j];
            float e = __uint_as_float(comp[4*i + j]);
            float wgt = 0.f;
            if (u >= thr_u[0]) wgt += c1 * e;
            if (u >= thr_u[1]) wgt += c2 * e;
            o[j] = wgt;
        }
        *(float4*)(base + 4*i) = make_float4(o[0], o[1], o[2], o[3]);
    }
    // pad cols [NP,NPP) keep raw score q.k_pad = 0 -> contribute 0 in wv
}

// ---------------- 7) out = W @ V (FFMA2, 128x32 tiles) ----------------------
#define WVA_STRIDE 260
#define WVB_STRIDE 36

__global__ __launch_bounds__(256) void wv_gemm() {
    __shared__ float AsD[32][WVA_STRIDE];   // dup'd weight rows
    __shared__ float Bs [32][WVB_STRIDE];   // v tile [k][d]
    int bh = blockIdx.y;
    int b = bh >> 3, h = bh & 7;
    int r0 = blockIdx.x * 128;
    const float* W = g_S + (size_t)bh*NPP*NPP;
    const float* V = g_v + (size_t)bh*NPP*DH;
    int tid = threadIdx.x;
    int tx = tid & 7;      // cols tx*4..+3
    int ty = tid >> 3;     // rows ty*4..+3

    ull acc[4][2];
    #pragma unroll
    for (int i = 0; i < 4; i++) { acc[i][0] = 0ull; acc[i][1] = 0ull; }

    for (int k0 = 0; k0 < NPP; k0 += 32) {
        #pragma unroll
        for (int l = 0; l < 16; l++) {
            int e = tid + l*256;
            int row = e >> 5, kk = e & 31;
            float v = W[(size_t)(r0 + row)*NPP + k0 + kk];
            *(float2*)&AsD[kk][2*row] = make_float2(v, v);
        }
        #pragma unroll
        for (int l = 0; l < 4; l++) {
            int e = tid + l*256;
            int kr = e >> 5, d = e & 31;
            Bs[kr][d] = V[(size_t)(k0 + kr)*DH + d];
        }
        __syncthreads();
        #pragma unroll 8
        for (int kk = 0; kk < 32; kk++) {
            ulonglong2 A0 = *(const ulonglong2*)&AsD[kk][8*ty];     // r0,r1 dup
            ulonglong2 A1 = *(const ulonglong2*)&AsD[kk][8*ty + 4]; // r2,r3 dup
            ulonglong2 Bv = *(const ulonglong2*)&Bs[kk][4*tx];      // (c0,c1),(c2,c3)
            fma2(acc[0][0], A0.x, Bv.x); fma2(acc[0][1], A0.x, Bv.y);
            fma2(acc[1][0], A0.y, Bv.x); fma2(acc[1][1], A0.y, Bv.y);
            fma2(acc[2][0], A1.x, Bv.x); fma2(acc[2][1], A1.x, Bv.y);
            fma2(acc[3][0], A1.y, Bv.x); fma2(acc[3][1], A1.y, Bv.y);
        }
        __syncthreads();
    }
    #pragma unroll
    for (int i = 0; i < 4; i++) {
        int nrow = r0 + ty*4 + i;
        float2 p0 = up2(acc[i][0]), p1 = up2(acc[i][1]);
        float4 o = make_float4(p0.x, p0.y, p1.x, p1.y);
        *(float4*)&g_ao[((size_t)b*NPP + nrow)*CH + h*DH + tx*4] = o;
    }
}

// ---------------- 8) projection + transposed store to [B,C,H,W] -------------
__global__ __launch_bounds__(256) void proj_gemm(const float* __restrict__ proj_w,
                                                 const float* __restrict__ proj_b,
                                                 float* __restrict__ out) {
    __shared__ float As[16][65];
    __shared__ float Bs[16][65];
    int b  = blockIdx.z;
    int m0 = blockIdx.x * 64;
    int o0 = blockIdx.y * 64;
    int tid = threadIdx.x, tx = tid & 15, ty = tid >> 4;
    float acc[4][4] = {};
    for (int k0 = 0; k0 < CH; k0 += 16) {
        #pragma unroll
        for (int l = 0; l < 4; l++) {
            int idx = tid + l*256; int k = idx & 15, m = idx >> 4;
            As[k][m] = g_ao[((size_t)b*NPP + m0 + m)*CH + k0 + k];
        }
        #pragma unroll
        for (int l = 0; l < 4; l++) {
            int idx = tid + l*256; int k = idx & 15, o = idx >> 4;
            Bs[k][o] = proj_w[(size_t)(o0 + o)*CH + k0 + k];
        }
        __syncthreads();
        #pragma unroll
        for (int kk = 0; kk < 16; kk++) {
            float a[4], bb[4];
            #pragma unroll
            for (int i = 0; i < 4; i++) a[i]  = As[kk][ty*4 + i];
            #pragma unroll
            for (int j = 0; j < 4; j++) bb[j] = Bs[kk][tx*4 + j];
            #pragma unroll
            for (int i = 0; i < 4; i++)
                #pragma unroll
                for (int j = 0; j < 4; j++) acc[i][j] += a[i]*bb[j];
        }
        __syncthreads();
    }
    #pragma unroll
    for (int i = 0; i < 4; i++) {
        int n = m0 + ty*4 + i;
        #pragma unroll
        for (int j = 0; j < 4; j++) {
            int o = o0 + tx*4 + j;
            out[((size_t)b*CH + o)*NP + n] = acc[i][j] + proj_b[o];
        }
    }
}

// ---------------------------------------------------------------------------
extern "C" void kernel_launch(void* const* d_in, const int* in_sizes, int n_in,
                              void* d_out, int out_size) {
    (void)in_sizes; (void)n_in; (void)out_size;
    const float* x      = (const float*)d_in[0];
    const float* y      = (const float*)d_in[1];
    const float* q_w    = (const float*)d_in[2];
    const float* q_b    = (const float*)d_in[3];
    const float* kv_w   = (const float*)d_in[4];
    const float* kv_b   = (const float*)d_in[5];
    const float* proj_w = (const float*)d_in[6];
    const float* proj_b = (const float*)d_in[7];
    const float* ln_w   = (const float*)d_in[8];
    const float* ln_b   = (const float*)d_in[9];
    const float* p1     = (const float*)d_in[10];
    const float* p2     = (const float*)d_in[11];
    float* out = (float*)d_out;

    cudaFuncSetAttribute(score_mma, cudaFuncAttributeMaxDynamicSharedMemorySize,
                         SC_SMEM_BYTES);

    pool_kernel<<<BATCH*CH, 256>>>(y);
    ln_kernel  <<<BATCH*NP, 256>>>(ln_w, ln_b);
    kv_gemm    <<<dim3(NP/64, 512/64, BATCH), 256>>>(kv_w, kv_b);
    q_gemm     <<<dim3(NP/64, CH/64, BATCH), 256>>>(x, q_w, q_b);
    score_mma  <<<dim3(NPP/128, NPP/128, BATCH*NH), 256, SC_SMEM_BYTES>>>();
    topk_kernel<<<BATCH*NH*NP, 256>>>(p1, p2);
    wv_gemm    <<<dim3(NPP/128, BATCH*NH), 256>>>();
    proj_gemm  <<<dim3(NP/64, CH/64, BATCH), 256>>>(proj_w, proj_b, out);
}

// round 12
// speedup vs baseline: 1.1189x; 1.1189x over previous
#include <cuda_runtime.h>
#include <math.h>
#include <stdint.h>

#define BATCH 2
#define CH 256
#define HH 56
#define WW 56
#define NP (HH*WW)        /* 3136 */
#define NPP 3200          /* padded token dim (25 * 128) */
#define NH 8
#define DH 32
#define KCNT1 1568        /* N1 // 2 */
#define KCNT2 1045        /* N1 // 3 */
#define LN_EPS 1e-5f
#define SCALE 0.17677669529663687f  /* 1/sqrt(32) */

typedef unsigned long long ull;

// ---------------- scratch (static device globals; no allocation) ------------
// Pad rows [NP, NPP) are NEVER written -> remain zero from static init.
__device__ __align__(16) float g_pool[BATCH*CH*NP];
__device__ __align__(16) float g_yln [BATCH*NP*CH];
__device__ __align__(16) float g_q   [BATCH*NH*NPP*DH];
__device__ __align__(16) float g_k   [BATCH*NH*NPP*DH];
__device__ __align__(16) float g_v   [BATCH*NH*NPP*DH];
__device__ __align__(16) float g_ao  [BATCH*NPP*CH];
__device__ __align__(16) float g_S   [(size_t)BATCH*NH*NPP*NPP];   // ~655 MB

// ---------------- 1) multiscale avg pool (3+5+7, zero-pad, divisor k^2) -----
__global__ __launch_bounds__(256) void pool_kernel(const float* __restrict__ y) {
    __shared__ float plane[NP];
    int bc = blockIdx.x;
    const float* src = y + (size_t)bc * NP;
    for (int i = threadIdx.x; i < NP; i += 256) plane[i] = src[i];
    __syncthreads();
    for (int i = threadIdx.x; i < NP; i += 256) {
        int r = i / WW, c = i % WW;
        float s3 = 0.f, s5 = 0.f, s7 = 0.f;
        #pragma unroll
        for (int dr = -3; dr <= 3; dr++) {
            int rr = r + dr; if (rr < 0 || rr >= HH) continue;
            #pragma unroll
            for (int dc = -3; dc <= 3; dc++) {
                int cc = c + dc; if (cc < 0 || cc >= WW) continue;
                float v = plane[rr*WW + cc];
                s7 += v;
                if (dr >= -2 && dr <= 2 && dc >= -2 && dc <= 2) s5 += v;
                if (dr >= -1 && dr <= 1 && dc >= -1 && dc <= 1) s3 += v;
            }
        }
        g_pool[(size_t)bc*NP + i] = s3*(1.f/9.f) + s5*(1.f/25.f) + s7*(1.f/49.f);
    }
}

// ---------------- 2) LayerNorm over channels -> yln [B,N,C] -----------------
__global__ __launch_bounds__(256) void ln_kernel(const float* __restrict__ ln_w,
                                                 const float* __restrict__ ln_b) {
    __shared__ float red[256];
    int bn = blockIdx.x;
    int b = bn / NP, n = bn % NP;
    int c = threadIdx.x;
    float v = g_pool[((size_t)b*CH + c)*NP + n];
    red[c] = v; __syncthreads();
    for (int off = 128; off > 0; off >>= 1) {
        if (c < off) red[c] += red[c + off];
        __syncthreads();
    }
    float mean = red[0] * (1.f/CH);
    __syncthreads();
    float dv = v - mean;
    red[c] = dv * dv; __syncthreads();
    for (int off = 128; off > 0; off >>= 1) {
        if (c < off) red[c] += red[c + off];
        __syncthreads();
    }
    float var = red[0] * (1.f/CH);
    g_yln[(size_t)bn*CH + c] = dv * rsqrtf(var + LN_EPS) * ln_w[c] + ln_b[c];
}

// ---------------- 3) KV GEMM: yln[B,N,C] x kv_w[512,C]^T -> k,v -------------
__global__ __launch_bounds__(256) void kv_gemm(const float* __restrict__ kv_w,
                                               const float* __restrict__ kv_b) {
    __shared__ float As[16][65];
    __shared__ float Bs[16][65];
    int b  = blockIdx.z;
    int m0 = blockIdx.x * 64;
    int o0 = blockIdx.y * 64;
    int tid = threadIdx.x, tx = tid & 15, ty = tid >> 4;
    float acc[4][4] = {};
    for (int k0 = 0; k0 < CH; k0 += 16) {
        #pragma unroll
        for (int l = 0; l < 4; l++) {
            int idx = tid + l*256; int k = idx & 15, m = idx >> 4;
            As[k][m] = g_yln[((size_t)b*NP + m0 + m)*CH + k0 + k];
        }
        #pragma unroll
        for (int l = 0; l < 4; l++) {
            int idx = tid + l*256; int k = idx & 15, o = idx >> 4;
            Bs[k][o] = kv_w[(size_t)(o0 + o)*CH + k0 + k];
        }
        __syncthreads();
        #pragma unroll
        for (int kk = 0; kk < 16; kk++) {
            float a[4], bb[4];
            #pragma unroll
            for (int i = 0; i < 4; i++) a[i]  = As[kk][ty*4 + i];
            #pragma unroll
            for (int j = 0; j < 4; j++) bb[j] = Bs[kk][tx*4 + j];
            #pragma unroll
            for (int i = 0; i < 4; i++)
                #pragma unroll
                for (int j = 0; j < 4; j++) acc[i][j] += a[i]*bb[j];
        }
        __syncthreads();
    }
    #pragma unroll
    for (int i = 0; i < 4; i++) {
        int n = m0 + ty*4 + i;
        #pragma unroll
        for (int j = 0; j < 4; j++) {
            int o = o0 + tx*4 + j;
            float r = acc[i][j] + kv_b[o];
            if (o < 256) {
                int hh = o >> 5, dd = o & 31;
                g_k[(((size_t)b*NH + hh)*NPP + n)*DH + dd] = r;
            } else {
                int oo = o - 256; int hh = oo >> 5, dd = oo & 31;
                g_v[(((size_t)b*NH + hh)*NPP + n)*DH + dd] = r;
            }
        }
    }
}

// ---------------- 4) Q GEMM: x[B,C,N] x q_w^T -------------------------------
__global__ __launch_bounds__(256) void q_gemm(const float* __restrict__ x,
                                              const float* __restrict__ q_w,
                                              const float* __restrict__ q_b) {
    __shared__ float As[16][65];
    __shared__ float Bs[16][65];
    int b  = blockIdx.z;
    int m0 = blockIdx.x * 64;
    int o0 = blockIdx.y * 64;
    const float* xb = x + (size_t)b*CH*NP;
    int tid = threadIdx.x, tx = tid & 15, ty = tid >> 4;
    float acc[4][4] = {};
    for (int k0 = 0; k0 < CH; k0 += 16) {
        #pragma unroll
        for (int l = 0; l < 4; l++) {
            int idx = tid + l*256; int m = idx & 63, k = idx >> 6;
            As[k][m] = xb[(size_t)(k0 + k)*NP + m0 + m];
        }
        #pragma unroll
        for (int l = 0; l < 4; l++) {
            int idx = tid + l*256; int k = idx & 15, o = idx >> 4;
            Bs[k][o] = q_w[(size_t)(o0 + o)*CH + k0 + k];
        }
        __syncthreads();
        #pragma unroll
        for (int kk = 0; kk < 16; kk++) {
            float a[4], bb[4];
            #pragma unroll
            for (int i = 0; i < 4; i++) a[i]  = As[kk][ty*4 + i];
            #pragma unroll
            for (int j = 0; j < 4; j++) bb[j] = Bs[kk][tx*4 + j];
            #pragma unroll
            for (int i = 0; i < 4; i++)
                #pragma unroll
                for (int j = 0; j < 4; j++) acc[i][j] += a[i]*bb[j];
        }
        __syncthreads();
    }
    #pragma unroll
    for (int i = 0; i < 4; i++) {
        int n = m0 + ty*4 + i;
        #pragma unroll
        for (int j = 0; j < 4; j++) {
            int o = o0 + tx*4 + j;
            int hh = o >> 5, dd = o & 31;
            g_q[(((size_t)b*NH + hh)*NPP + n)*DH + dd] = acc[i][j] + q_b[o];
        }
    }
}

// ====== shared helpers: bf16 split + mma.sync =================================
__device__ __forceinline__ void sc_bfsplit(float v, unsigned &hi16, unsigned &lo16) {
    unsigned u = __float_as_uint(v);
    unsigned t = u + 0x7FFFu + ((u >> 16) & 1u);
    hi16 = t >> 16;
    float r = v - __uint_as_float(hi16 << 16);
    unsigned ur = __float_as_uint(r);
    unsigned tr = ur + 0x7FFFu + ((ur >> 16) & 1u);
    lo16 = tr >> 16;
}

__device__ __forceinline__ void mma_bf16(float* d, const unsigned* a, const unsigned* b) {
    asm volatile(
        "mma.sync.aligned.m16n8k16.row.col.f32.bf16.bf16.f32 "
        "{%0,%1,%2,%3}, {%4,%5,%6,%7}, {%8,%9}, {%0,%1,%2,%3};"
        : "+f"(d[0]), "+f"(d[1]), "+f"(d[2]), "+f"(d[3])
        : "r"(a[0]), "r"(a[1]), "r"(a[2]), "r"(a[3]), "r"(b[0]), "r"(b[1]));
}

// ====== 5) scores via mma.sync bf16-split (128x128 tile, 8 warps) ===========
// A' = [q_hi | q_hi | q_lo] (K=96), B' = [k_hi | k_lo | k_hi] (K=96)
// D = q_hi*k_hi + q_hi*k_lo + q_lo*k_hi  (fp32 accumulate)

#define SC_STRIDE 52   /* 32-bit words per row: 48 data + 4 pad (conflict-free) */
#define SC_SMEM_BYTES (2 * 128 * SC_STRIDE * 4)

__global__ __launch_bounds__(256) void score_mma() {
    extern __shared__ unsigned sm32[];
    unsigned (*As)[SC_STRIDE] = (unsigned(*)[SC_STRIDE])sm32;              // q' [row][kw]
    unsigned (*Bs)[SC_STRIDE] = (unsigned(*)[SC_STRIDE])(sm32 + 128*SC_STRIDE); // k'

    int tid = threadIdx.x;
    int bh = blockIdx.z;
    int n0 = blockIdx.x * 128;
    int m0 = blockIdx.y * 128;

    // -------- load + split phase: 2048 chunks of 2 floats each --------------
    {
        const float* qb = g_q + ((size_t)bh*NPP + n0)*DH;
        const float* kb = g_k + ((size_t)bh*NPP + m0)*DH;
        #pragma unroll
        for (int l = 0; l < 8; l++) {
            int ch = tid + l*256;
            int row = ch >> 4, c2 = ch & 15;
            float2 qv = *(const float2*)(qb + (size_t)row*DH + 2*c2);
            float2 kv = *(const float2*)(kb + (size_t)row*DH + 2*c2);
            unsigned qh0, ql0, qh1, ql1, kh0, kl0, kh1, kl1;
            sc_bfsplit(qv.x, qh0, ql0); sc_bfsplit(qv.y, qh1, ql1);
            sc_bfsplit(kv.x, kh0, kl0); sc_bfsplit(kv.y, kh1, kl1);
            unsigned qh = qh0 | (qh1 << 16), ql = ql0 | (ql1 << 16);
            unsigned kh = kh0 | (kh1 << 16), kl = kl0 | (kl1 << 16);
            As[row][c2]      = qh;   // K 0..31 : q_hi
            As[row][16 + c2] = qh;   // K 32..63: q_hi
            As[row][32 + c2] = ql;   // K 64..95: q_lo
            Bs[row][c2]      = kh;   // K 0..31 : k_hi
            Bs[row][16 + c2] = kl;   // K 32..63: k_lo
            Bs[row][32 + c2] = kh;   // K 64..95: k_hi
        }
    }
    __syncthreads();

    // -------- compute phase: warp = 32 rows x 64 cols ----------------------
    int wid = tid >> 5, lane = tid & 31;
    int g = lane >> 2, tig = lane & 3;
    int warpM = wid & 3, warpN = wid >> 2;
    int mrow = warpM * 32;
    int ncol = warpN * 64;

    float acc[2][8][4];
    #pragma unroll
    for (int i = 0; i < 2; i++)
        #pragma unroll
        for (int j = 0; j < 8; j++)
            #pragma unroll
            for (int q = 0; q < 4; q++) acc[i][j][q] = 0.f;

    #pragma unroll
    for (int ks = 0; ks < 6; ks++) {
        int w0 = ks * 8;
        unsigned af[2][4];
        #pragma unroll
        for (int mt = 0; mt < 2; mt++) {
            int r = mrow + mt*16 + g;
            af[mt][0] = As[r][w0 + tig];
            af[mt][1] = As[r + 8][w0 + tig];
            af[mt][2] = As[r][w0 + tig + 4];
            af[mt][3] = As[r + 8][w0 + tig + 4];
        }
        #pragma unroll
        for (int nt = 0; nt < 8; nt++) {
            unsigned bf[2];
            int n = ncol + nt*8 + g;
            bf[0] = Bs[n][w0 + tig];
            bf[1] = Bs[n][w0 + tig + 4];
            mma_bf16(acc[0][nt], af[0], bf);
            mma_bf16(acc[1][nt], af[1], bf);
        }
    }

    // -------- epilogue -----------------------------------------------------
    float* outb = g_S + ((size_t)bh*NPP + n0)*NPP + m0;
    #pragma unroll
    for (int mt = 0; mt < 2; mt++) {
        int r0 = mrow + mt*16 + g;
        #pragma unroll
        for (int nt = 0; nt < 8; nt++) {
            int c = ncol + nt*8 + tig*2;
            float2 lo = make_float2(acc[mt][nt][0]*SCALE, acc[mt][nt][1]*SCALE);
            float2 hi = make_float2(acc[mt][nt][2]*SCALE, acc[mt][nt][3]*SCALE);
            *(float2*)(outb + (size_t)r0*NPP + c)       = lo;
            *(float2*)(outb + (size_t)(r0 + 8)*NPP + c) = hi;
        }
    }
}

// ---------------- 6) per-row exact top-k thresholds + combined weights ------
// (R8 structure; only the final store changed: weights are written as packed
//  split-bf16 pairs (hi16<<16)|lo16 so wv_mma needs no float conversion.)
__device__ __forceinline__ unsigned block_suffix(unsigned h, int tid,
                                                 unsigned* wsum, unsigned* whigh) {
    unsigned v = h;
    int lane = tid & 31, w = tid >> 5;
    #pragma unroll
    for (int off = 1; off < 32; off <<= 1) {
        unsigned u = __shfl_down_sync(0xFFFFFFFFu, v, off);
        if (lane + off < 32) v += u;
    }
    if (lane == 0) wsum[w] = v;
    __syncthreads();
    if (tid == 0) {
        unsigned run = 0;
        for (int j = 7; j >= 0; j--) { whigh[j] = run; run += wsum[j]; }
    }
    __syncthreads();
    return v + whigh[w];
}

__global__ __launch_bounds__(256) void topk_kernel(const float* __restrict__ p1p,
                                                   const float* __restrict__ p2p) {
    __shared__ unsigned su[NP];
    __shared__ float    sf[NP];
    __shared__ unsigned hist[256];
    __shared__ unsigned wsum[8], whigh[8];
    __shared__ float f8a[8], f8b[8];
    __shared__ unsigned selB_sh; __shared__ int selR_sh;
    __shared__ unsigned l0B[2];  __shared__ int l0R[2];
    __shared__ unsigned umax_sh;

    int bid = blockIdx.x;
    int head = bid / NP, n = bid % NP;
    float* base = g_S + ((size_t)head*NPP + n)*NPP;
    int tid = threadIdx.x;
    int lane = tid & 31, w = tid >> 5;

    // vectorized load + monotonic transform; track max
    unsigned lmax = 0u;
    const float4* b4 = (const float4*)base;
    for (int i = tid; i < NP/4; i += 256) {
        float4 v4 = b4[i];
        float vv[4] = {v4.x, v4.y, v4.z, v4.w};
        #pragma unroll
        for (int j = 0; j < 4; j++) {
            unsigned u = __float_as_uint(vv[j]);
            u ^= (u & 0x80000000u) ? 0xFFFFFFFFu : 0x80000000u;
            su[4*i + j] = u;
            sf[4*i + j] = vv[j];
            lmax = max(lmax, u);
        }
    }
    #pragma unroll
    for (int off = 16; off > 0; off >>= 1)
        lmax = max(lmax, __shfl_xor_sync(0xFFFFFFFFu, lmax, off));
    if (lane == 0) wsum[w] = lmax;
    __syncthreads();
    if (tid == 0) {
        unsigned m = 0u;
        for (int j = 0; j < 8; j++) m = max(m, wsum[j]);
        umax_sh = m;
    }
    __syncthreads();
    unsigned umax = umax_sh;
    float rowmax = __uint_as_float(umax ^ ((umax & 0x80000000u) ? 0x80000000u : 0xFFFFFFFFu));
    __syncthreads();

    // ---- level 0 (bits 31..24) shared by both selections ----
    hist[tid] = 0u; __syncthreads();
    for (int i = tid; i < NP; i += 256)
        atomicAdd(&hist[su[i] >> 24], 1u);
    __syncthreads();
    {
        unsigned h = hist[tid];
        unsigned v = block_suffix(h, tid, wsum, whigh);
        if (v >= (unsigned)KCNT1 && v - h < (unsigned)KCNT1) {
            l0B[0] = (unsigned)tid; l0R[0] = KCNT1 - (int)(v - h);
        }
        if (v >= (unsigned)KCNT2 && v - h < (unsigned)KCNT2) {
            l0B[1] = (unsigned)tid; l0R[1] = KCNT2 - (int)(v - h);
        }
    }
    __syncthreads();

    unsigned thr_u[2];
    for (int s = 0; s < 2; s++) {
        unsigned prefix = l0B[s] << 24;
        unsigned mask   = 0xFF000000u;
        int r = l0R[s];
        for (int shift = 16; shift >= 0; shift -= 8) {
            hist[tid] = 0u; __syncthreads();
            for (int i = tid; i < NP; i += 256) {
                unsigned u = su[i];
                if ((u & mask) == prefix)
                    atomicAdd(&hist[(u >> shift) & 255u], 1u);
            }
            __syncthreads();
            unsigned h = hist[tid];
            unsigned v = block_suffix(h, tid, wsum, whigh);
            if (v >= (unsigned)r && v - h < (unsigned)r) {
                selB_sh = (unsigned)tid;
                selR_sh = r - (int)(v - h);
            }
            __syncthreads();
            prefix |= selB_sh << shift;
            mask   |= 0xFFu << shift;
            r = selR_sh;
        }
        thr_u[s] = prefix;
    }
    __syncthreads();

    // Z1, Z2
    float z1 = 0.f, z2 = 0.f;
    for (int i = tid; i < NP; i += 256) {
        unsigned u = su[i];
        float e = __expf(sf[i] - rowmax);
        if (u >= thr_u[0]) z1 += e;
        if (u >= thr_u[1]) z2 += e;
    }
    #pragma unroll
    for (int off = 16; off > 0; off >>= 1) {
        z1 += __shfl_xor_sync(0xFFFFFFFFu, z1, off);
        z2 += __shfl_xor_sync(0xFFFFFFFFu, z2, off);
    }
    if (lane == 0) { f8a[w] = z1; f8b[w] = z2; }
    __syncthreads();
    float Z1 = 0.f, Z2 = 0.f;
    #pragma unroll
    for (int j = 0; j < 8; j++) { Z1 += f8a[j]; Z2 += f8b[j]; }

    float c1 = p1p[0] / Z1;
    float c2 = p2p[0] / Z2;
    unsigned* baseu = (unsigned*)base;
    for (int i = tid; i < NP; i += 256) {
        unsigned u = su[i];
        float e = __expf(sf[i] - rowmax);
        float wgt = 0.f;
        if (u >= thr_u[0]) wgt += c1 * e;
        if (u >= thr_u[1]) wgt += c2 * e;
        unsigned hi, lo;
        sc_bfsplit(wgt, hi, lo);
        baseu[i] = (hi << 16) | lo;
    }
    // pad cols [NP,NPP) hold raw score 0.0f = packed(0,0) -> zero in wv
}

// ====== 7) out = W @ V via mma.sync, W pre-split by topk ====================
// A' = [w_hi|w_hi|w_lo] built with bit-ops only; B' = [v_hi|v_lo|v_hi]
#define WV_STRIDE 52

__global__ __launch_bounds__(256) void wv_mma() {
    __shared__ unsigned As[128][WV_STRIDE];   // W' rows
    __shared__ unsigned Bs[32][WV_STRIDE];    // V' (n-major)
    int tid = threadIdx.x;
    int bh = blockIdx.y;
    int b = bh >> 3, h = bh & 7;
    int r0 = blockIdx.x * 128;
    const unsigned* W = (const unsigned*)g_S + (size_t)bh*NPP*NPP + (size_t)r0*NPP;
    const float* V = g_v + (size_t)bh*NPP*DH;

    int wid = tid >> 5, lane = tid & 31;
    int g = lane >> 2, tig = lane & 3;
    int mrow = wid * 16;   // each warp: 16 rows x 32 cols

    float acc[4][4];
    #pragma unroll
    for (int j = 0; j < 4; j++)
        #pragma unroll
        for (int q = 0; q < 4; q++) acc[j][q] = 0.f;

    for (int k0 = 0; k0 < NPP; k0 += 32) {
        // ---- W: 128 rows x 32 packed u32 -> A' via bit-ops ------------
        #pragma unroll
        for (int l = 0; l < 8; l++) {
            int ch = tid + l*256;           // 0..2047
            int row = ch >> 4, c2 = ch & 15;
            uint2 wp = *(const uint2*)(W + (size_t)row*NPP + k0 + 2*c2);
            unsigned hw = (wp.x >> 16) | (wp.y & 0xFFFF0000u);
            unsigned lw = (wp.x & 0xFFFFu) | (wp.y << 16);
            As[row][c2]      = hw;
            As[row][16 + c2] = hw;
            As[row][32 + c2] = lw;
        }
        // ---- V: 32 rows(k) x 32 cols(d) -> transpose into B'[d][kw] ----
        #pragma unroll
        for (int l = 0; l < 2; l++) {
            int ch = tid + l*256;           // 0..511
            int kr = ch >> 4, c2 = ch & 15;
            float2 vv = *(const float2*)(V + (size_t)(k0 + kr)*DH + 2*c2);
            unsigned h0, l0w, h1, l1w;
            sc_bfsplit(vv.x, h0, l0w); sc_bfsplit(vv.y, h1, l1w);
            unsigned short* bp = (unsigned short*)&Bs[0][0];
            int wkw = kr >> 1, hs = kr & 1;
            int hoff0 = ((2*c2)     * WV_STRIDE + wkw)*2 + hs;
            int hoff1 = ((2*c2 + 1) * WV_STRIDE + wkw)*2 + hs;
            bp[hoff0]      = (unsigned short)h0;   // region 0: v_hi
            bp[hoff0 + 32] = (unsigned short)l0w;  // region 1: v_lo (+16 words)
            bp[hoff0 + 64] = (unsigned short)h0;   // region 2: v_hi (+32 words)
            bp[hoff1]      = (unsigned short)h1;
            bp[hoff1 + 32] = (unsigned short)l1w;
            bp[hoff1 + 64] = (unsigned short)h1;
        }
        __syncthreads();

        #pragma unroll
        for (int ks = 0; ks < 6; ks++) {
            int w0 = ks * 8;
            unsigned af[4];
            int r = mrow + g;
            af[0] = As[r][w0 + tig];
            af[1] = As[r + 8][w0 + tig];
            af[2] = As[r][w0 + tig + 4];
            af[3] = As[r + 8][w0 + tig + 4];
            #pragma unroll
            for (int nt = 0; nt < 4; nt++) {
                unsigned bf[2];
                int n = nt*8 + g;
                bf[0] = Bs[n][w0 + tig];
                bf[1] = Bs[n][w0 + tig + 4];
                mma_bf16(acc[nt], af, bf);
            }
        }
        __syncthreads();
    }

    // ---- epilogue: rows r0+mrow+g, +8; cols nt*8+tig*2 --------------------
    #pragma unroll
    for (int nt = 0; nt < 4; nt++) {
        int c = nt*8 + tig*2;
        int rlo = r0 + mrow + g;
        float2 lo = make_float2(acc[nt][0], acc[nt][1]);
        float2 hi = make_float2(acc[nt][2], acc[nt][3]);
        *(float2*)&g_ao[((size_t)b*NPP + rlo)*CH + h*DH + c]     = lo;
        *(float2*)&g_ao[((size_t)b*NPP + rlo + 8)*CH + h*DH + c] = hi;
    }
}

// ---------------- 8) projection + transposed store to [B,C,H,W] -------------
__global__ __launch_bounds__(256) void proj_gemm(const float* __restrict__ proj_w,
                                                 const float* __restrict__ proj_b,
                                                 float* __restrict__ out) {
    __shared__ float As[16][65];
    __shared__ float Bs[16][65];
    int b  = blockIdx.z;
    int m0 = blockIdx.x * 64;
    int o0 = blockIdx.y * 64;
    int tid = threadIdx.x, tx = tid & 15, ty = tid >> 4;
    float acc[4][4] = {};
    for (int k0 = 0; k0 < CH; k0 += 16) {
        #pragma unroll
        for (int l = 0; l < 4; l++) {
            int idx = tid + l*256; int k = idx & 15, m = idx >> 4;
            As[k][m] = g_ao[((size_t)b*NPP + m0 + m)*CH + k0 + k];
        }
        #pragma unroll
        for (int l = 0; l < 4; l++) {
            int idx = tid + l*256; int k = idx & 15, o = idx >> 4;
            Bs[k][o] = proj_w[(size_t)(o0 + o)*CH + k0 + k];
        }
        __syncthreads();
        #pragma unroll
        for (int kk = 0; kk < 16; kk++) {
            float a[4], bb[4];
            #pragma unroll
            for (int i = 0; i < 4; i++) a[i]  = As[kk][ty*4 + i];
            #pragma unroll
            for (int j = 0; j < 4; j++) bb[j] = Bs[kk][tx*4 + j];
            #pragma unroll
            for (int i = 0; i < 4; i++)
                #pragma unroll
                for (int j = 0; j < 4; j++) acc[i][j] += a[i]*bb[j];
        }
        __syncthreads();
    }
    #pragma unroll
    for (int i = 0; i < 4; i++) {
        int n = m0 + ty*4 + i;
        #pragma unroll
        for (int j = 0; j < 4; j++) {
            int o = o0 + tx*4 + j;
            out[((size_t)b*CH + o)*NP + n] = acc[i][j] + proj_b[o];
        }
    }
}

// ---------------------------------------------------------------------------
extern "C" void kernel_launch(void* const* d_in, const int* in_sizes, int n_in,
                              void* d_out, int out_size) {
    (void)in_sizes; (void)n_in; (void)out_size;
    const float* x      = (const float*)d_in[0];
    const float* y      = (const float*)d_in[1];
    const float* q_w    = (const float*)d_in[2];
    const float* q_b    = (const float*)d_in[3];
    const float* kv_w   = (const float*)d_in[4];
    const float* kv_b   = (const float*)d_in[5];
    const float* proj_w = (const float*)d_in[6];
    const float* proj_b = (const float*)d_in[7];
    const float* ln_w   = (const float*)d_in[8];
    const float* ln_b   = (const float*)d_in[9];
    const float* p1     = (const float*)d_in[10];
    const float* p2     = (const float*)d_in[11];
    float* out = (float*)d_out;

    cudaFuncSetAttribute(score_mma, cudaFuncAttributeMaxDynamicSharedMemorySize,
                         SC_SMEM_BYTES);

    pool_kernel<<<BATCH*CH, 256>>>(y);
    ln_kernel  <<<BATCH*NP, 256>>>(ln_w, ln_b);
    kv_gemm    <<<dim3(NP/64, 512/64, BATCH), 256>>>(kv_w, kv_b);
    q_gemm     <<<dim3(NP/64, CH/64, BATCH), 256>>>(x, q_w, q_b);
    score_mma  <<<dim3(NPP/128, NPP/128, BATCH*NH), 256, SC_SMEM_BYTES>>>();
    topk_kernel<<<BATCH*NH*NP, 256>>>(p1, p2);
    wv_mma     <<<dim3(NPP/128, BATCH*NH), 256>>>();
    proj_gemm  <<<dim3(NP/64, CH/64, BATCH), 256>>>(proj_w, proj_b, out);
}